// round 5
// baseline (speedup 1.0000x reference)
#include <cuda_runtime.h>

// WideAndDeepModel fused v3, sm_103a.
// 128 persistent CTAs x 512 threads, 2 tiles of 64 rows each.
// All weights pre-packed in SMEM as f32x2 pairs (ull) with BN folded in, so
// every inner-loop weight load is a warp-uniform LDS128 feeding fma.rn.f32x2
// directly (zero MOVs). Activations stored transposed+duplicated with stride
// 134 (bank-step 6 -> 2-way store conflicts max). Warp owns output columns,
// lane owns a row: per k-step L1 = 1 LDS64 + 4 uniform LDS128 + 8 FFMA2.

#define TILE    64
#define THREADS 512
#define GRID    128
#define TPC     2

#define XTS 134            // dup stride (rows*2 + pad), even, bank-step 6
#define H3S 36

// SMEM float offsets
#define OFF_W1P 0          // ull[164][64]  = 20992 floats
#define OFF_B1P 20992      // ull[64]       = 128
#define OFF_W2P 21120      // ull[128][32]  = 8192
#define OFF_B2P 29312      // ull[32]       = 64
#define OFF_W3P 29376      // ull[64][16]   = 2048
#define OFF_B3  31424      // 32
#define OFF_W4  31456      // 32
#define OFF_R1  31488      // xT dup 164*134=21976 >= h1d 128*134 >= h2d 64*134 + h3
#define OFF_H3  (OFF_R1 + 64 * XTS)
#define OFF_IDS 53464      // 256 ints
#define SMEM_FLOATS 53720
#define SMEM_BYTES (SMEM_FLOATS * 4)

typedef unsigned long long ull;

__device__ __forceinline__ ull pk2(float a, float b) {
    ull r;
    asm("mov.b64 %0, {%1, %2};" : "=l"(r) : "f"(a), "f"(b));
    return r;
}
__device__ __forceinline__ void upk2(ull v, float& a, float& b) {
    asm("mov.b64 {%0, %1}, %2;" : "=f"(a), "=f"(b) : "l"(v));
}
__device__ __forceinline__ void ffma2(ull& d, ull a, ull b) {
    asm("fma.rn.f32x2 %0, %1, %2, %0;" : "+l"(d) : "l"(a), "l"(b));
}

extern __shared__ float sm[];

__global__ void __launch_bounds__(THREADS, 1)
wd_fused_v3(const float* __restrict__ user,
            const float* __restrict__ price,
            const float* __restrict__ temporal,
            const float* __restrict__ item_emb,
            const float* __restrict__ cat_emb,
            const float* __restrict__ wide1,
            const float* __restrict__ wide2,
            const float* __restrict__ crossW,
            const int*   __restrict__ item_ids,
            const int*   __restrict__ cat_ids,
            const int*   __restrict__ wf1,
            const int*   __restrict__ wf2,
            const float* __restrict__ W1, const float* __restrict__ b1,
            const float* __restrict__ W2, const float* __restrict__ b2,
            const float* __restrict__ W3, const float* __restrict__ b3,
            const float* __restrict__ W4, const float* __restrict__ b4,
            const float* __restrict__ g1, const float* __restrict__ be1,
            const float* __restrict__ g2, const float* __restrict__ be2,
            const float* __restrict__ g3, const float* __restrict__ be3,
            float* __restrict__ out) {
    int* idsm = (int*)(sm + OFF_IDS);
    const int tid  = threadIdx.x;
    const int lane = tid & 31;
    const int w    = tid >> 5;
    const float inv = rsqrtf(1.0f + 1e-5f);

    // ---- pre-pack weights as (c, c+1) f32x2 pairs, BN folded ----
    for (int i = tid; i < 164 * 64; i += THREADS) {
        int k = i >> 6, p = i & 63, c = 2 * p;
        sm[OFF_W1P + 2 * i]     = W1[k * 128 + c]     * (g1[c]     * inv);
        sm[OFF_W1P + 2 * i + 1] = W1[k * 128 + c + 1] * (g1[c + 1] * inv);
    }
    for (int i = tid; i < 128 * 32; i += THREADS) {
        int k = i >> 5, p = i & 31, c = 2 * p;
        sm[OFF_W2P + 2 * i]     = W2[k * 64 + c]     * (g2[c]     * inv);
        sm[OFF_W2P + 2 * i + 1] = W2[k * 64 + c + 1] * (g2[c + 1] * inv);
    }
    for (int i = tid; i < 64 * 16; i += THREADS) {
        int k = i >> 4, p = i & 15, c = 2 * p;
        sm[OFF_W3P + 2 * i]     = W3[k * 32 + c]     * (g3[c]     * inv);
        sm[OFF_W3P + 2 * i + 1] = W3[k * 32 + c + 1] * (g3[c + 1] * inv);
    }
    if (tid < 128) sm[OFF_B1P + tid] = b1[tid] * (g1[tid] * inv) + be1[tid];
    if (tid < 64)  sm[OFF_B2P + tid] = b2[tid] * (g2[tid] * inv) + be2[tid];
    if (tid < 32) {
        sm[OFF_B3 + tid] = b3[tid] * (g3[tid] * inv) + be3[tid];
        sm[OFF_W4 + tid] = W4[tid];
    }
    const float b4v = b4[0];

    const int cg = w & 7;          // L1 colgroup: cols [16cg,16cg+16)
    const int h  = w >> 3;         // row half
    const int r  = lane + 32 * h;  // this thread's row (L1/L2)

    for (int t = 0; t < TPC; ++t) {
        const int base = (blockIdx.x + t * GRID) * TILE;
        __syncthreads();

        if (tid < 256) {
            int which = tid >> 6, rr = tid & 63;
            const int* p = which == 0 ? item_ids : which == 1 ? cat_ids
                         : which == 2 ? wf1 : wf2;
            idsm[tid] = p[base + rr];
        }
        __syncthreads();

        float wv1 = 0.f, wv2 = 0.f, wcx = 0.f;
        if (tid < 64) {
            int f1 = idsm[128 + tid];
            int f2 = idsm[192 + tid];
            wv1 = wide1[f1];
            wv2 = wide2[f2];
            wcx = crossW[(long long)f1 * 10000 + f2];
        }

        // ---- gather into xT dup: xT[feat][2row] = (v,v) ----
        float* R1 = sm + OFF_R1;
#pragma unroll
        for (int i = 0; i < 8; ++i) {               // user 64x64
            int idx = tid + i * 512;
            int rr = idx >> 6, c = idx & 63;
            float v = user[(base + rr) * 64 + c];
            *(ull*)(R1 + c * XTS + 2 * rr) = pk2(v, v);
        }
#pragma unroll
        for (int i = 0; i < 8; ++i) {               // item 64x64
            int idx = tid + i * 512;
            int rr = idx >> 6, c = idx & 63;
            long long id = idsm[rr];
            float v = item_emb[id * 64 + c];
            *(ull*)(R1 + (64 + c) * XTS + 2 * rr) = pk2(v, v);
        }
#pragma unroll
        for (int i = 0; i < 4; ++i) {               // cat 64x32
            int idx = tid + i * 512;
            int rr = idx >> 5, c = idx & 31;
            int id = idsm[64 + rr];
            float v = cat_emb[id * 32 + c];
            *(ull*)(R1 + (128 + c) * XTS + 2 * rr) = pk2(v, v);
        }
        if (tid < 128) {                            // price/temporal 64x2
            int rr = tid >> 1, c = tid & 1;
            float v = price[(base + rr) * 2 + c];
            *(ull*)(R1 + (160 + c) * XTS + 2 * rr) = pk2(v, v);
            float v2 = temporal[(base + rr) * 2 + c];
            *(ull*)(R1 + (162 + c) * XTS + 2 * rr) = pk2(v2, v2);
        }
        __syncthreads();

        // ---- L1: [64x164]@[164x128]; warp=16 cols, lane=1 row ----
        ull a[8];
#pragma unroll
        for (int i = 0; i < 8; ++i) a[i] = 0ull;
        {
            const ull* wp = (const ull*)(sm + OFF_W1P) + 8 * cg;
            const float* xp = R1 + 2 * r;
#pragma unroll 4
            for (int k = 0; k < 164; ++k) {
                ull x = *(const ull*)(xp + k * XTS);
                ulonglong2 w01 = *(const ulonglong2*)(wp + k * 64);
                ulonglong2 w23 = *(const ulonglong2*)(wp + k * 64 + 2);
                ulonglong2 w45 = *(const ulonglong2*)(wp + k * 64 + 4);
                ulonglong2 w67 = *(const ulonglong2*)(wp + k * 64 + 6);
                ffma2(a[0], x, w01.x); ffma2(a[1], x, w01.y);
                ffma2(a[2], x, w23.x); ffma2(a[3], x, w23.y);
                ffma2(a[4], x, w45.x); ffma2(a[5], x, w45.y);
                ffma2(a[6], x, w67.x); ffma2(a[7], x, w67.y);
            }
        }
        __syncthreads();   // xT dead -> overwrite with h1 dup

        {
            const float* bp = sm + OFF_B1P + 16 * cg;
#pragma unroll
            for (int j = 0; j < 8; ++j) {
                float v0, v1;
                upk2(a[j], v0, v1);
                v0 = fmaxf(v0 + bp[2 * j], 0.f);
                v1 = fmaxf(v1 + bp[2 * j + 1], 0.f);
                int c0 = 16 * cg + 2 * j;
                *(ull*)(R1 + c0 * XTS + 2 * r)       = pk2(v0, v0);
                *(ull*)(R1 + (c0 + 1) * XTS + 2 * r) = pk2(v1, v1);
            }
        }
        __syncthreads();

        // ---- L2: [64x128]@[128x64]; warp=8 cols, lane=1 row ----
        ull c2[4];
#pragma unroll
        for (int i = 0; i < 4; ++i) c2[i] = 0ull;
        {
            const ull* wp2 = (const ull*)(sm + OFF_W2P) + 4 * cg;
            const float* hp = R1 + 2 * r;
#pragma unroll 4
            for (int k = 0; k < 128; ++k) {
                ull x = *(const ull*)(hp + k * XTS);
                ulonglong2 wa = *(const ulonglong2*)(wp2 + k * 32);
                ulonglong2 wb = *(const ulonglong2*)(wp2 + k * 32 + 2);
                ffma2(c2[0], x, wa.x); ffma2(c2[1], x, wa.y);
                ffma2(c2[2], x, wb.x); ffma2(c2[3], x, wb.y);
            }
        }
        __syncthreads();   // h1 dead -> overwrite with h2 dup

        {
            const float* bp = sm + OFF_B2P + 8 * cg;
#pragma unroll
            for (int j = 0; j < 4; ++j) {
                float v0, v1;
                upk2(c2[j], v0, v1);
                v0 = fmaxf(v0 + bp[2 * j], 0.f);
                v1 = fmaxf(v1 + bp[2 * j + 1], 0.f);
                int c0 = 8 * cg + 2 * j;
                *(ull*)(R1 + c0 * XTS + 2 * r)       = pk2(v0, v0);
                *(ull*)(R1 + (c0 + 1) * XTS + 2 * r) = pk2(v1, v1);
            }
        }
        __syncthreads();

        // ---- L3: [64x64]@[64x32]; warp=4 rows, lane: row 4w+(lane>>3), cols 4q ----
        {
            const int q  = lane & 7;
            const int rr = 4 * w + (lane >> 3);
            ull d0 = 0ull, d1 = 0ull;
            const ull* wp3 = (const ull*)(sm + OFF_W3P) + 2 * q;
            const float* hp3 = R1 + 2 * rr;
#pragma unroll 4
            for (int k = 0; k < 64; ++k) {
                ull x = *(const ull*)(hp3 + k * XTS);
                ulonglong2 wv = *(const ulonglong2*)(wp3 + k * 16);
                ffma2(d0, x, wv.x);
                ffma2(d1, x, wv.y);
            }
            const float* bp = sm + OFF_B3 + 4 * q;
            float v0, v1, v2, v3;
            upk2(d0, v0, v1);
            upk2(d1, v2, v3);
            float4 o;
            o.x = fmaxf(v0 + bp[0], 0.f);
            o.y = fmaxf(v1 + bp[1], 0.f);
            o.z = fmaxf(v2 + bp[2], 0.f);
            o.w = fmaxf(v3 + bp[3], 0.f);
            *(float4*)(sm + OFF_H3 + rr * H3S + 4 * q) = o;  // disjoint from h2
        }
        __syncthreads();

        // ---- L4 (32->1) + wide ----
        if (tid < 64) {
            const float* hr = sm + OFF_H3 + tid * H3S;
            const float* w4s = sm + OFF_W4;
            float s0 = 0.f, s1 = 0.f, s2 = 0.f, s3 = 0.f;
#pragma unroll
            for (int k = 0; k < 32; k += 4) {
                s0 = fmaf(hr[k],     w4s[k],     s0);
                s1 = fmaf(hr[k + 1], w4s[k + 1], s1);
                s2 = fmaf(hr[k + 2], w4s[k + 2], s2);
                s3 = fmaf(hr[k + 3], w4s[k + 3], s3);
            }
            out[base + tid] = (s0 + s1) + (s2 + s3) + b4v + wv1 + wv2 + wcx;
        }
    }
}

extern "C" void kernel_launch(void* const* d_in, const int* in_sizes, int n_in,
                              void* d_out, int out_size) {
    (void)in_sizes; (void)n_in; (void)out_size;
    static bool attr_set = false;
    if (!attr_set) {
        cudaFuncSetAttribute(wd_fused_v3,
                             cudaFuncAttributeMaxDynamicSharedMemorySize, SMEM_BYTES);
        attr_set = true;
    }
    wd_fused_v3<<<GRID, THREADS, SMEM_BYTES>>>(
        (const float*)d_in[0], (const float*)d_in[1], (const float*)d_in[2],
        (const float*)d_in[3], (const float*)d_in[4], (const float*)d_in[5],
        (const float*)d_in[6], (const float*)d_in[7],
        (const int*)d_in[8], (const int*)d_in[9], (const int*)d_in[10],
        (const int*)d_in[11],
        (const float*)d_in[12], (const float*)d_in[13],
        (const float*)d_in[14], (const float*)d_in[15],
        (const float*)d_in[16], (const float*)d_in[17],
        (const float*)d_in[18], (const float*)d_in[19],
        (const float*)d_in[20], (const float*)d_in[21],
        (const float*)d_in[22], (const float*)d_in[23],
        (const float*)d_in[24], (const float*)d_in[25],
        (float*)d_out);
}

// round 10
// speedup vs baseline: 1.5463x; 1.5463x over previous
#include <cuda_runtime.h>

// WideAndDeepModel fused v4, sm_103a.
// 128 CTAs x 512 threads, ONE 128-row tile per CTA (no outer loop).
// Crossbar-optimized: activations transposed NON-duplicated (stride 132);
// each lane owns 2 adjacent rows -> one LDS64 feeds 2 rows, duplicated into
// packed f32x2 registers with MOVs (issue is not the bottleneck, the 128B/cyc
// crossbar is). Weights pre-packed as f32x2 col-pairs, loaded warp-uniformly
// (broadcast, 1 wavefront per LDS128). L1: 6 wf per 16 FFMA2 per warp.

#define THREADS 512
#define GRID    128
#define XS      132          // transposed activation stride (128 rows + pad)
#define H3S     36

// SMEM float offsets
#define OFF_W1P 0            // ull[164][64]  = 20992 floats
#define OFF_B1P 20992        // 128
#define OFF_W2P 21120        // ull[128][32]  = 8192
#define OFF_B2P 29312        // 64
#define OFF_W3P 29376        // ull[64][16]   = 2048
#define OFF_B3  31424        // 32
#define OFF_W4  31456        // 32
#define OFF_R1  31488        // xT[164][132]=21648 >= h1T[128][132] >= h2T[64][132]+h3
#define OFF_H3  (OFF_R1 + 64 * XS)          // h3: [128][36] after h2T
#define OFF_IDS (OFF_R1 + 21648)            // 512 ints
#define SMEM_FLOATS (OFF_IDS + 512)
#define SMEM_BYTES (SMEM_FLOATS * 4)

typedef unsigned long long ull;

__device__ __forceinline__ ull pk2(float a, float b) {
    ull r;
    asm("mov.b64 %0, {%1, %2};" : "=l"(r) : "f"(a), "f"(b));
    return r;
}
__device__ __forceinline__ void upk2(ull v, float& a, float& b) {
    asm("mov.b64 {%0, %1}, %2;" : "=f"(a), "=f"(b) : "l"(v));
}
__device__ __forceinline__ void ffma2(ull& d, ull a, ull b) {
    asm("fma.rn.f32x2 %0, %1, %2, %0;" : "+l"(d) : "l"(a), "l"(b));
}

extern __shared__ float sm[];

__global__ void __launch_bounds__(THREADS, 1)
wd_fused_v4(const float* __restrict__ user,
            const float* __restrict__ price,
            const float* __restrict__ temporal,
            const float* __restrict__ item_emb,
            const float* __restrict__ cat_emb,
            const float* __restrict__ wide1,
            const float* __restrict__ wide2,
            const float* __restrict__ crossW,
            const int*   __restrict__ item_ids,
            const int*   __restrict__ cat_ids,
            const int*   __restrict__ wf1,
            const int*   __restrict__ wf2,
            const float* __restrict__ W1, const float* __restrict__ b1,
            const float* __restrict__ W2, const float* __restrict__ b2,
            const float* __restrict__ W3, const float* __restrict__ b3,
            const float* __restrict__ W4, const float* __restrict__ b4,
            const float* __restrict__ g1, const float* __restrict__ be1,
            const float* __restrict__ g2, const float* __restrict__ be2,
            const float* __restrict__ g3, const float* __restrict__ be3,
            float* __restrict__ out) {
    int* idsm = (int*)(sm + OFF_IDS);
    float* R1 = sm + OFF_R1;
    const int tid  = threadIdx.x;
    const int lane = tid & 31;
    const int w    = tid >> 5;
    const int cg   = w & 7;             // column group
    const int rg   = w >> 3;            // row group (0/1)
    const int off  = 64 * rg + 2 * lane;  // this lane's row pair base
    const float inv = rsqrtf(1.0f + 1e-5f);
    const int base = blockIdx.x * 128;

    // ---- pre-pack weights as (c,c+1) f32x2 pairs, BN folded ----
    for (int i = tid; i < 164 * 64; i += THREADS) {
        int k = i >> 6, p = i & 63, c = 2 * p;
        sm[OFF_W1P + 2 * i]     = W1[k * 128 + c]     * (g1[c]     * inv);
        sm[OFF_W1P + 2 * i + 1] = W1[k * 128 + c + 1] * (g1[c + 1] * inv);
    }
    for (int i = tid; i < 128 * 32; i += THREADS) {
        int k = i >> 5, p = i & 31, c = 2 * p;
        sm[OFF_W2P + 2 * i]     = W2[k * 64 + c]     * (g2[c]     * inv);
        sm[OFF_W2P + 2 * i + 1] = W2[k * 64 + c + 1] * (g2[c + 1] * inv);
    }
    for (int i = tid; i < 64 * 16; i += THREADS) {
        int k = i >> 4, p = i & 15, c = 2 * p;
        sm[OFF_W3P + 2 * i]     = W3[k * 32 + c]     * (g3[c]     * inv);
        sm[OFF_W3P + 2 * i + 1] = W3[k * 32 + c + 1] * (g3[c + 1] * inv);
    }
    if (tid < 128) sm[OFF_B1P + tid] = b1[tid] * (g1[tid] * inv) + be1[tid];
    if (tid < 64)  sm[OFF_B2P + tid] = b2[tid] * (g2[tid] * inv) + be2[tid];
    if (tid < 32) {
        sm[OFF_B3 + tid] = b3[tid] * (g3[tid] * inv) + be3[tid];
        sm[OFF_W4 + tid] = W4[tid];
    }
    const float b4v = b4[0];

    // ---- ids: item[0:128) cat[128:256) f1[256:384) f2[384:512) ----
    {
        int which = tid >> 7, rr = tid & 127;
        const int* p = which == 0 ? item_ids : which == 1 ? cat_ids
                     : which == 2 ? wf1 : wf2;
        idsm[tid] = p[base + rr];
    }
    __syncthreads();

    // ---- wide prefetch (held in regs; latency hidden under gather) ----
    float wv1 = 0.f, wv2 = 0.f, wcx = 0.f;
    if (tid < 128) {
        int f1 = idsm[256 + tid];
        int f2 = idsm[384 + tid];
        wv1 = wide1[f1];
        wv2 = wide2[f2];
        wcx = crossW[(long long)f1 * 10000 + f2];
    }

    // ---- gather into xT (non-dup): xT[feat][row] ----
#pragma unroll
    for (int i = 0; i < 16; ++i) {              // user 128x64
        int idx = tid + i * 512;
        int r = idx >> 6, c = idx & 63;
        R1[c * XS + r] = user[(base + r) * 64 + c];
    }
#pragma unroll
    for (int i = 0; i < 16; ++i) {              // item 128x64 (gather)
        int idx = tid + i * 512;
        int r = idx >> 6, c = idx & 63;
        long long id = idsm[r];
        R1[(64 + c) * XS + r] = item_emb[id * 64 + c];
    }
#pragma unroll
    for (int i = 0; i < 8; ++i) {               // cat 128x32 (gather)
        int idx = tid + i * 512;
        int r = idx >> 5, c = idx & 31;
        int id = idsm[128 + r];
        R1[(128 + c) * XS + r] = cat_emb[id * 32 + c];
    }
    if (tid < 256) {                            // price/temporal 128x2
        int r = tid >> 1, c = tid & 1;
        R1[(160 + c) * XS + r] = price[(base + r) * 2 + c];
        R1[(162 + c) * XS + r] = temporal[(base + r) * 2 + c];
    }
    __syncthreads();

    // ---- L1: [128x164]@[164x128]; warp = 16 cols x 64 rows (2 rows/lane) ----
    ull a0[8], a1[8];
#pragma unroll
    for (int i = 0; i < 8; ++i) { a0[i] = 0ull; a1[i] = 0ull; }
    {
        const ull* wp = (const ull*)(sm + OFF_W1P) + 8 * cg;
        const float* xr = R1 + off;
#pragma unroll 4
        for (int k = 0; k < 164; ++k) {
            float2 xv = *(const float2*)(xr + k * XS);
            ull xd0 = pk2(xv.x, xv.x);
            ull xd1 = pk2(xv.y, xv.y);
            ulonglong2 wA = *(const ulonglong2*)(wp + k * 64);
            ulonglong2 wB = *(const ulonglong2*)(wp + k * 64 + 2);
            ulonglong2 wC = *(const ulonglong2*)(wp + k * 64 + 4);
            ulonglong2 wD = *(const ulonglong2*)(wp + k * 64 + 6);
            ffma2(a0[0], xd0, wA.x); ffma2(a1[0], xd1, wA.x);
            ffma2(a0[1], xd0, wA.y); ffma2(a1[1], xd1, wA.y);
            ffma2(a0[2], xd0, wB.x); ffma2(a1[2], xd1, wB.x);
            ffma2(a0[3], xd0, wB.y); ffma2(a1[3], xd1, wB.y);
            ffma2(a0[4], xd0, wC.x); ffma2(a1[4], xd1, wC.x);
            ffma2(a0[5], xd0, wC.y); ffma2(a1[5], xd1, wC.y);
            ffma2(a0[6], xd0, wD.x); ffma2(a1[6], xd1, wD.x);
            ffma2(a0[7], xd0, wD.y); ffma2(a1[7], xd1, wD.y);
        }
    }
    __syncthreads();   // xT dead -> overwrite with h1T

    {   // h1T store (bias+relu), non-dup: pk2(row r0, row r1) per col
        const float2* bp = (const float2*)(sm + OFF_B1P + 16 * cg);
#pragma unroll
        for (int j = 0; j < 8; ++j) {
            float2 bj = bp[j];
            float p, q, s, t;
            upk2(a0[j], p, q);   // row r0: cols c0, c0+1
            upk2(a1[j], s, t);   // row r1
            int c0 = 16 * cg + 2 * j;
            float v00 = fmaxf(p + bj.x, 0.f), v10 = fmaxf(s + bj.x, 0.f);
            float v01 = fmaxf(q + bj.y, 0.f), v11 = fmaxf(t + bj.y, 0.f);
            *(ull*)(R1 + c0 * XS + off)       = pk2(v00, v10);
            *(ull*)(R1 + (c0 + 1) * XS + off) = pk2(v01, v11);
        }
    }
    __syncthreads();

    // ---- L2: [128x128]@[128x64]; warp = 8 cols x 64 rows ----
    ull c0_[4], c1_[4];
#pragma unroll
    for (int i = 0; i < 4; ++i) { c0_[i] = 0ull; c1_[i] = 0ull; }
    {
        const ull* wp2 = (const ull*)(sm + OFF_W2P) + 4 * cg;
        const float* hr = R1 + off;
#pragma unroll 4
        for (int k = 0; k < 128; ++k) {
            float2 xv = *(const float2*)(hr + k * XS);
            ull xd0 = pk2(xv.x, xv.x);
            ull xd1 = pk2(xv.y, xv.y);
            ulonglong2 wA = *(const ulonglong2*)(wp2 + k * 32);
            ulonglong2 wB = *(const ulonglong2*)(wp2 + k * 32 + 2);
            ffma2(c0_[0], xd0, wA.x); ffma2(c1_[0], xd1, wA.x);
            ffma2(c0_[1], xd0, wA.y); ffma2(c1_[1], xd1, wA.y);
            ffma2(c0_[2], xd0, wB.x); ffma2(c1_[2], xd1, wB.x);
            ffma2(c0_[3], xd0, wB.y); ffma2(c1_[3], xd1, wB.y);
        }
    }
    __syncthreads();   // h1T dead -> overwrite with h2T

    {   // h2T store (bias+relu)
        const float2* bp = (const float2*)(sm + OFF_B2P + 8 * cg);
#pragma unroll
        for (int j = 0; j < 4; ++j) {
            float2 bj = bp[j];
            float p, q, s, t;
            upk2(c0_[j], p, q);
            upk2(c1_[j], s, t);
            int c0 = 8 * cg + 2 * j;
            float v00 = fmaxf(p + bj.x, 0.f), v10 = fmaxf(s + bj.x, 0.f);
            float v01 = fmaxf(q + bj.y, 0.f), v11 = fmaxf(t + bj.y, 0.f);
            *(ull*)(R1 + c0 * XS + off)       = pk2(v00, v10);
            *(ull*)(R1 + (c0 + 1) * XS + off) = pk2(v01, v11);
        }
    }
    __syncthreads();

    // ---- L3: [128x64]@[64x32]; warp = 4 cols x 64 rows ----
    {
        ull d00 = 0ull, d01 = 0ull, d10 = 0ull, d11 = 0ull;
        const ull* wp3 = (const ull*)(sm + OFF_W3P) + 2 * cg;
        const float* hr = R1 + off;
#pragma unroll 4
        for (int k = 0; k < 64; ++k) {
            float2 xv = *(const float2*)(hr + k * XS);
            ull xd0 = pk2(xv.x, xv.x);
            ull xd1 = pk2(xv.y, xv.y);
            ulonglong2 wv = *(const ulonglong2*)(wp3 + k * 16);
            ffma2(d00, xd0, wv.x); ffma2(d10, xd1, wv.x);
            ffma2(d01, xd0, wv.y); ffma2(d11, xd1, wv.y);
        }
        // h3 region [OFF_H3, +128*36) is disjoint from live h2T -> direct store
        const float4 bv = *(const float4*)(sm + OFF_B3 + 4 * cg);
        float p, q, s, t;
        float4 o;
        upk2(d00, p, q); upk2(d01, s, t);            // row r0, cols 4cg..4cg+3
        o.x = fmaxf(p + bv.x, 0.f); o.y = fmaxf(q + bv.y, 0.f);
        o.z = fmaxf(s + bv.z, 0.f); o.w = fmaxf(t + bv.w, 0.f);
        *(float4*)(sm + OFF_H3 + (off + 0) * H3S + 4 * cg) = o;
        upk2(d10, p, q); upk2(d11, s, t);            // row r1
        o.x = fmaxf(p + bv.x, 0.f); o.y = fmaxf(q + bv.y, 0.f);
        o.z = fmaxf(s + bv.z, 0.f); o.w = fmaxf(t + bv.w, 0.f);
        *(float4*)(sm + OFF_H3 + (off + 1) * H3S + 4 * cg) = o;
    }
    __syncthreads();

    // ---- L4 (32->1) + wide; one thread per row ----
    if (tid < 128) {
        const float* hr = sm + OFF_H3 + tid * H3S;
        const float* w4s = sm + OFF_W4;
        float s0 = 0.f, s1 = 0.f, s2 = 0.f, s3 = 0.f;
#pragma unroll
        for (int k = 0; k < 32; k += 4) {
            s0 = fmaf(hr[k],     w4s[k],     s0);
            s1 = fmaf(hr[k + 1], w4s[k + 1], s1);
            s2 = fmaf(hr[k + 2], w4s[k + 2], s2);
            s3 = fmaf(hr[k + 3], w4s[k + 3], s3);
        }
        out[base + tid] = (s0 + s1) + (s2 + s3) + b4v + wv1 + wv2 + wcx;
    }
}

extern "C" void kernel_launch(void* const* d_in, const int* in_sizes, int n_in,
                              void* d_out, int out_size) {
    (void)in_sizes; (void)n_in; (void)out_size;
    static bool attr_set = false;
    if (!attr_set) {
        cudaFuncSetAttribute(wd_fused_v4,
                             cudaFuncAttributeMaxDynamicSharedMemorySize, SMEM_BYTES);
        attr_set = true;
    }
    wd_fused_v4<<<GRID, THREADS, SMEM_BYTES>>>(
        (const float*)d_in[0], (const float*)d_in[1], (const float*)d_in[2],
        (const float*)d_in[3], (const float*)d_in[4], (const float*)d_in[5],
        (const float*)d_in[6], (const float*)d_in[7],
        (const int*)d_in[8], (const int*)d_in[9], (const int*)d_in[10],
        (const int*)d_in[11],
        (const float*)d_in[12], (const float*)d_in[13],
        (const float*)d_in[14], (const float*)d_in[15],
        (const float*)d_in[16], (const float*)d_in[17],
        (const float*)d_in[18], (const float*)d_in[19],
        (const float*)d_in[20], (const float*)d_in[21],
        (const float*)d_in[22], (const float*)d_in[23],
        (const float*)d_in[24], (const float*)d_in[25],
        (float*)d_out);
}

// round 14
// speedup vs baseline: 1.6795x; 1.0862x over previous
#include <cuda_runtime.h>

// WideAndDeepModel fused v5, sm_103a. (Re-submit: R13 was an infra failure,
// this source was never measured.)
// v4 skeleton (128 CTAs x 512 thr, one 128-row tile, transposed non-dup
// activations, f32x2-packed warp-uniform weights) with:
//  - XS=134 (bank step 6): transpose stores 2-way instead of 8-way conflicted
//  - register-staged user/item gathers (16 LDGs in flight before stores)
//  - unroll 8 on L2/L3 inner loops

#define THREADS 512
#define GRID    128
#define XS      134          // transposed activation stride: bank step 6 -> 2-way STS
#define H3S     36

// SMEM float offsets
#define OFF_W1P 0            // ull[164][64]  = 20992 floats
#define OFF_B1P 20992        // 128
#define OFF_W2P 21120        // ull[128][32]  = 8192
#define OFF_B2P 29312        // 64
#define OFF_W3P 29376        // ull[64][16]   = 2048
#define OFF_B3  31424        // 32
#define OFF_W4  31456        // 32
#define OFF_R1  31488        // xT[164][134]=21976 >= h1T[128][134] >= h2T[64][134]
#define OFF_H3  (OFF_R1 + 64 * XS)          // h3[128][36] after live h2T
#define OFF_IDS (OFF_R1 + 164 * XS)         // 512 ints
#define SMEM_FLOATS (OFF_IDS + 512)
#define SMEM_BYTES (SMEM_FLOATS * 4)

typedef unsigned long long ull;

__device__ __forceinline__ ull pk2(float a, float b) {
    ull r;
    asm("mov.b64 %0, {%1, %2};" : "=l"(r) : "f"(a), "f"(b));
    return r;
}
__device__ __forceinline__ void upk2(ull v, float& a, float& b) {
    asm("mov.b64 {%0, %1}, %2;" : "=f"(a), "=f"(b) : "l"(v));
}
__device__ __forceinline__ void ffma2(ull& d, ull a, ull b) {
    asm("fma.rn.f32x2 %0, %1, %2, %0;" : "+l"(d) : "l"(a), "l"(b));
}

extern __shared__ float sm[];

__global__ void __launch_bounds__(THREADS, 1)
wd_fused_v5(const float* __restrict__ user,
            const float* __restrict__ price,
            const float* __restrict__ temporal,
            const float* __restrict__ item_emb,
            const float* __restrict__ cat_emb,
            const float* __restrict__ wide1,
            const float* __restrict__ wide2,
            const float* __restrict__ crossW,
            const int*   __restrict__ item_ids,
            const int*   __restrict__ cat_ids,
            const int*   __restrict__ wf1,
            const int*   __restrict__ wf2,
            const float* __restrict__ W1, const float* __restrict__ b1,
            const float* __restrict__ W2, const float* __restrict__ b2,
            const float* __restrict__ W3, const float* __restrict__ b3,
            const float* __restrict__ W4, const float* __restrict__ b4,
            const float* __restrict__ g1, const float* __restrict__ be1,
            const float* __restrict__ g2, const float* __restrict__ be2,
            const float* __restrict__ g3, const float* __restrict__ be3,
            float* __restrict__ out) {
    int* idsm = (int*)(sm + OFF_IDS);
    float* R1 = sm + OFF_R1;
    const int tid  = threadIdx.x;
    const int lane = tid & 31;
    const int w    = tid >> 5;
    const int cg   = w & 7;               // column group
    const int rg   = w >> 3;              // row group (0/1)
    const int off  = 64 * rg + 2 * lane;  // this lane's row-pair base
    const float inv = rsqrtf(1.0f + 1e-5f);
    const int base = blockIdx.x * 128;

    // ---- ids first (earliest dependency) ----
    {
        int which = tid >> 7, rr = tid & 127;
        const int* p = which == 0 ? item_ids : which == 1 ? cat_ids
                     : which == 2 ? wf1 : wf2;
        idsm[tid] = p[base + rr];
    }

    // ---- pre-pack weights as (c,c+1) f32x2 pairs, BN folded ----
    for (int i = tid; i < 164 * 64; i += THREADS) {
        int k = i >> 6, p = i & 63, c = 2 * p;
        sm[OFF_W1P + 2 * i]     = W1[k * 128 + c]     * (g1[c]     * inv);
        sm[OFF_W1P + 2 * i + 1] = W1[k * 128 + c + 1] * (g1[c + 1] * inv);
    }
    for (int i = tid; i < 128 * 32; i += THREADS) {
        int k = i >> 5, p = i & 31, c = 2 * p;
        sm[OFF_W2P + 2 * i]     = W2[k * 64 + c]     * (g2[c]     * inv);
        sm[OFF_W2P + 2 * i + 1] = W2[k * 64 + c + 1] * (g2[c + 1] * inv);
    }
    for (int i = tid; i < 64 * 16; i += THREADS) {
        int k = i >> 4, p = i & 15, c = 2 * p;
        sm[OFF_W3P + 2 * i]     = W3[k * 32 + c]     * (g3[c]     * inv);
        sm[OFF_W3P + 2 * i + 1] = W3[k * 32 + c + 1] * (g3[c + 1] * inv);
    }
    if (tid < 128) sm[OFF_B1P + tid] = b1[tid] * (g1[tid] * inv) + be1[tid];
    if (tid < 64)  sm[OFF_B2P + tid] = b2[tid] * (g2[tid] * inv) + be2[tid];
    if (tid < 32) {
        sm[OFF_B3 + tid] = b3[tid] * (g3[tid] * inv) + be3[tid];
        sm[OFF_W4 + tid] = W4[tid];
    }
    const float b4v = b4[0];
    __syncthreads();

    // ---- wide prefetch (held in regs until epilogue) ----
    float wv1 = 0.f, wv2 = 0.f, wcx = 0.f;
    if (tid < 128) {
        int f1 = idsm[256 + tid];
        int f2 = idsm[384 + tid];
        wv1 = wide1[f1];
        wv2 = wide2[f2];
        wcx = crossW[(long long)f1 * 10000 + f2];
    }

    // ---- gather into xT (non-dup): xT[feat][row]; reg-staged for MLP ----
    {
        float uv[16];
#pragma unroll
        for (int i = 0; i < 16; ++i) {          // user 128x64, coalesced
            int idx = tid + i * 512;
            int r = idx >> 6, c = idx & 63;
            uv[i] = user[(base + r) * 64 + c];
        }
#pragma unroll
        for (int i = 0; i < 16; ++i) {
            int idx = tid + i * 512;
            int r = idx >> 6, c = idx & 63;
            R1[c * XS + r] = uv[i];
        }
    }
    {
        float iv[16];
#pragma unroll
        for (int i = 0; i < 16; ++i) {          // item 128x64, random rows
            int idx = tid + i * 512;
            int r = idx >> 6, c = idx & 63;
            iv[i] = item_emb[(long long)idsm[r] * 64 + c];
        }
#pragma unroll
        for (int i = 0; i < 16; ++i) {
            int idx = tid + i * 512;
            int r = idx >> 6, c = idx & 63;
            R1[(64 + c) * XS + r] = iv[i];
        }
    }
    {
        float cv[8];
#pragma unroll
        for (int i = 0; i < 8; ++i) {           // cat 128x32
            int idx = tid + i * 512;
            int r = idx >> 5, c = idx & 31;
            cv[i] = cat_emb[idsm[128 + r] * 32 + c];
        }
#pragma unroll
        for (int i = 0; i < 8; ++i) {
            int idx = tid + i * 512;
            int r = idx >> 5, c = idx & 31;
            R1[(128 + c) * XS + r] = cv[i];
        }
    }
    if (tid < 256) {                            // price/temporal 128x2
        int r = tid >> 1, c = tid & 1;
        R1[(160 + c) * XS + r] = price[(base + r) * 2 + c];
        R1[(162 + c) * XS + r] = temporal[(base + r) * 2 + c];
    }
    __syncthreads();

    // ---- L1: [128x164]@[164x128]; warp = 16 cols x 64 rows (2 rows/lane) ----
    ull a0[8], a1[8];
#pragma unroll
    for (int i = 0; i < 8; ++i) { a0[i] = 0ull; a1[i] = 0ull; }
    {
        const ull* wp = (const ull*)(sm + OFF_W1P) + 8 * cg;
        const float* xr = R1 + off;
#pragma unroll 4
        for (int k = 0; k < 164; ++k) {
            float2 xv = *(const float2*)(xr + k * XS);
            ull xd0 = pk2(xv.x, xv.x);
            ull xd1 = pk2(xv.y, xv.y);
            ulonglong2 wA = *(const ulonglong2*)(wp + k * 64);
            ulonglong2 wB = *(const ulonglong2*)(wp + k * 64 + 2);
            ulonglong2 wC = *(const ulonglong2*)(wp + k * 64 + 4);
            ulonglong2 wD = *(const ulonglong2*)(wp + k * 64 + 6);
            ffma2(a0[0], xd0, wA.x); ffma2(a1[0], xd1, wA.x);
            ffma2(a0[1], xd0, wA.y); ffma2(a1[1], xd1, wA.y);
            ffma2(a0[2], xd0, wB.x); ffma2(a1[2], xd1, wB.x);
            ffma2(a0[3], xd0, wB.y); ffma2(a1[3], xd1, wB.y);
            ffma2(a0[4], xd0, wC.x); ffma2(a1[4], xd1, wC.x);
            ffma2(a0[5], xd0, wC.y); ffma2(a1[5], xd1, wC.y);
            ffma2(a0[6], xd0, wD.x); ffma2(a1[6], xd1, wD.x);
            ffma2(a0[7], xd0, wD.y); ffma2(a1[7], xd1, wD.y);
        }
    }
    __syncthreads();   // xT dead -> overwrite with h1T

    {   // h1T store (bias+relu): pk2(row r0, row r1) per col
        const float2* bp = (const float2*)(sm + OFF_B1P + 16 * cg);
#pragma unroll
        for (int j = 0; j < 8; ++j) {
            float2 bj = bp[j];
            float p, q, s, t;
            upk2(a0[j], p, q);
            upk2(a1[j], s, t);
            int c0 = 16 * cg + 2 * j;
            float v00 = fmaxf(p + bj.x, 0.f), v10 = fmaxf(s + bj.x, 0.f);
            float v01 = fmaxf(q + bj.y, 0.f), v11 = fmaxf(t + bj.y, 0.f);
            *(ull*)(R1 + c0 * XS + off)       = pk2(v00, v10);
            *(ull*)(R1 + (c0 + 1) * XS + off) = pk2(v01, v11);
        }
    }
    __syncthreads();

    // ---- L2: [128x128]@[128x64]; warp = 8 cols x 64 rows ----
    ull c0_[4], c1_[4];
#pragma unroll
    for (int i = 0; i < 4; ++i) { c0_[i] = 0ull; c1_[i] = 0ull; }
    {
        const ull* wp2 = (const ull*)(sm + OFF_W2P) + 4 * cg;
        const float* hr = R1 + off;
#pragma unroll 8
        for (int k = 0; k < 128; ++k) {
            float2 xv = *(const float2*)(hr + k * XS);
            ull xd0 = pk2(xv.x, xv.x);
            ull xd1 = pk2(xv.y, xv.y);
            ulonglong2 wA = *(const ulonglong2*)(wp2 + k * 32);
            ulonglong2 wB = *(const ulonglong2*)(wp2 + k * 32 + 2);
            ffma2(c0_[0], xd0, wA.x); ffma2(c1_[0], xd1, wA.x);
            ffma2(c0_[1], xd0, wA.y); ffma2(c1_[1], xd1, wA.y);
            ffma2(c0_[2], xd0, wB.x); ffma2(c1_[2], xd1, wB.x);
            ffma2(c0_[3], xd0, wB.y); ffma2(c1_[3], xd1, wB.y);
        }
    }
    __syncthreads();   // h1T dead -> overwrite with h2T

    {   // h2T store (bias+relu)
        const float2* bp = (const float2*)(sm + OFF_B2P + 8 * cg);
#pragma unroll
        for (int j = 0; j < 4; ++j) {
            float2 bj = bp[j];
            float p, q, s, t;
            upk2(c0_[j], p, q);
            upk2(c1_[j], s, t);
            int c0 = 8 * cg + 2 * j;
            float v00 = fmaxf(p + bj.x, 0.f), v10 = fmaxf(s + bj.x, 0.f);
            float v01 = fmaxf(q + bj.y, 0.f), v11 = fmaxf(t + bj.y, 0.f);
            *(ull*)(R1 + c0 * XS + off)       = pk2(v00, v10);
            *(ull*)(R1 + (c0 + 1) * XS + off) = pk2(v01, v11);
        }
    }
    __syncthreads();

    // ---- L3: [128x64]@[64x32]; warp = 4 cols x 64 rows ----
    {
        ull d00 = 0ull, d01 = 0ull, d10 = 0ull, d11 = 0ull;
        const ull* wp3 = (const ull*)(sm + OFF_W3P) + 2 * cg;
        const float* hr = R1 + off;
#pragma unroll 8
        for (int k = 0; k < 64; ++k) {
            float2 xv = *(const float2*)(hr + k * XS);
            ull xd0 = pk2(xv.x, xv.x);
            ull xd1 = pk2(xv.y, xv.y);
            ulonglong2 wv = *(const ulonglong2*)(wp3 + k * 16);
            ffma2(d00, xd0, wv.x); ffma2(d10, xd1, wv.x);
            ffma2(d01, xd0, wv.y); ffma2(d11, xd1, wv.y);
        }
        // h3 region is disjoint from live h2T -> direct store
        const float4 bv = *(const float4*)(sm + OFF_B3 + 4 * cg);
        float p, q, s, t;
        float4 o;
        upk2(d00, p, q); upk2(d01, s, t);            // row r0
        o.x = fmaxf(p + bv.x, 0.f); o.y = fmaxf(q + bv.y, 0.f);
        o.z = fmaxf(s + bv.z, 0.f); o.w = fmaxf(t + bv.w, 0.f);
        *(float4*)(sm + OFF_H3 + (off + 0) * H3S + 4 * cg) = o;
        upk2(d10, p, q); upk2(d11, s, t);            // row r1
        o.x = fmaxf(p + bv.x, 0.f); o.y = fmaxf(q + bv.y, 0.f);
        o.z = fmaxf(s + bv.z, 0.f); o.w = fmaxf(t + bv.w, 0.f);
        *(float4*)(sm + OFF_H3 + (off + 1) * H3S + 4 * cg) = o;
    }
    __syncthreads();

    // ---- L4 (32->1) + wide; one thread per row ----
    if (tid < 128) {
        const float* hr = sm + OFF_H3 + tid * H3S;
        const float* w4s = sm + OFF_W4;
        float s0 = 0.f, s1 = 0.f, s2 = 0.f, s3 = 0.f;
#pragma unroll
        for (int k = 0; k < 32; k += 4) {
            s0 = fmaf(hr[k],     w4s[k],     s0);
            s1 = fmaf(hr[k + 1], w4s[k + 1], s1);
            s2 = fmaf(hr[k + 2], w4s[k + 2], s2);
            s3 = fmaf(hr[k + 3], w4s[k + 3], s3);
        }
        out[base + tid] = (s0 + s1) + (s2 + s3) + b4v + wv1 + wv2 + wcx;
    }
}

extern "C" void kernel_launch(void* const* d_in, const int* in_sizes, int n_in,
                              void* d_out, int out_size) {
    (void)in_sizes; (void)n_in; (void)out_size;
    static bool attr_set = false;
    if (!attr_set) {
        cudaFuncSetAttribute(wd_fused_v5,
                             cudaFuncAttributeMaxDynamicSharedMemorySize, SMEM_BYTES);
        attr_set = true;
    }
    wd_fused_v5<<<GRID, THREADS, SMEM_BYTES>>>(
        (const float*)d_in[0], (const float*)d_in[1], (const float*)d_in[2],
        (const float*)d_in[3], (const float*)d_in[4], (const float*)d_in[5],
        (const float*)d_in[6], (const float*)d_in[7],
        (const int*)d_in[8], (const int*)d_in[9], (const int*)d_in[10],
        (const int*)d_in[11],
        (const float*)d_in[12], (const float*)d_in[13],
        (const float*)d_in[14], (const float*)d_in[15],
        (const float*)d_in[16], (const float*)d_in[17],
        (const float*)d_in[18], (const float*)d_in[19],
        (const float*)d_in[20], (const float*)d_in[21],
        (const float*)d_in[22], (const float*)d_in[23],
        (const float*)d_in[24], (const float*)d_in[25],
        (float*)d_out);
}